// round 14
// baseline (speedup 1.0000x reference)
#include <cuda_runtime.h>
#include <cuda_fp16.h>
#include <cstdint>

#define RANK    64
#define WIN     11
#define TILE    128
#define THREADS 256
#define NROWS   144     // staged rows; buffer row br <-> global row tile_start + br - 5
#define XSH     72      // xh row stride in halves (144B, 16B-aligned)
#define ROW16B  (16 * XSH * 2)   // 2304: byte stride of 16 rows

// smem byte offsets
#define XH_OFF   0                    // fp16 X tile: 144*144 = 20736
#define WH_OFF   20736                // fp16 W: 64*144 = 9216
#define BS_OFF   29952                // bias fp32, 256B
#define SMEM_BYTES 30208

// softmax exp base-2 scale: (1/sqrt(64)) * log2(e)
#define EXP2_SCALE 0.18033688011112042f

#define LDSM_X4(r0, r1, r2, r3, a) \
    asm volatile("ldmatrix.sync.aligned.m8n8.x4.shared.b16 {%0,%1,%2,%3}, [%4];" \
        : "=r"(r0), "=r"(r1), "=r"(r2), "=r"(r3) : "r"(a))
#define LDSM_X4T(r0, r1, r2, r3, a) \
    asm volatile("ldmatrix.sync.aligned.m8n8.x4.trans.shared.b16 {%0,%1,%2,%3}, [%4];" \
        : "=r"(r0), "=r"(r1), "=r"(r2), "=r"(r3) : "r"(a))
#define HMMA16(d, a0, a1, a2, a3, b0, b1) \
    asm volatile("mma.sync.aligned.m16n8k16.row.col.f32.f16.f16.f32 " \
        "{%0,%1,%2,%3},{%4,%5,%6,%7},{%8,%9},{%0,%1,%2,%3};" \
        : "+f"((d)[0]), "+f"((d)[1]), "+f"((d)[2]), "+f"((d)[3]) \
        : "r"(a0), "r"(a1), "r"(a2), "r"(a3), "r"(b0), "r"(b1))

__device__ __forceinline__ uint32_t sptr(const void* p) {
    return (uint32_t)__cvta_generic_to_shared(p);
}
__device__ __forceinline__ uint32_t h2bits(__half2 h) {
    return *reinterpret_cast<uint32_t*>(&h);
}
__device__ __forceinline__ float hw_tanh(float x) {
    float r;
    asm("tanh.approx.f32 %0, %1;" : "=f"(r) : "f"(x));
    return r;
}
__device__ __forceinline__ float ex2f(float x) {
    float r;
    asm("ex2.approx.f32 %0, %1;" : "=f"(r) : "f"(x));
    return r;
}

__global__ void __launch_bounds__(THREADS) attn_window_kernel(
    const float* __restrict__ X,   // (L, 64)
    const float* __restrict__ W,   // (64, 64) row-major (out, in)
    const float* __restrict__ b,   // (64,)
    float* __restrict__ out,       // (L, 64)
    int length)
{
    extern __shared__ __align__(16) char sm[];
    __half* xh  = (__half*)(sm + XH_OFF);
    __half* wh  = (__half*)(sm + WH_OFF);
    float*  bsm = (float*)(sm + BS_OFF);

    const int tid  = threadIdx.x;
    const int lane = tid & 31;
    const int wid  = tid >> 5;
    const int gid  = lane >> 2;      // mma group id (0..7)
    const int tg   = lane & 3;       // thread-in-group (0..3)
    const int mat  = lane >> 3;      // ldmatrix matrix id (0..3)
    const int mrow = lane & 7;       // ldmatrix row within matrix
    const int tile_start = blockIdx.x * TILE;
    const int m0 = wid * 16;         // warp's first local row

    // ---- stage X as fp16: interior CTAs skip per-row predication ----
    const bool interior = (tile_start >= 5) && (tile_start + NROWS - 5 <= length);
    if (interior) {
        const float* xb = &X[(size_t)(tile_start - 5) * RANK];
        #pragma unroll
        for (int i = 0; i < 9; i++) {
            int idx = tid + i * THREADS;
            int br  = idx >> 4;
            int col = (idx & 15) << 2;
            float4 v = *reinterpret_cast<const float4*>(&xb[br * RANK + col]);
            uint2 hv;
            hv.x = h2bits(__floats2half2_rn(v.x, v.y));
            hv.y = h2bits(__floats2half2_rn(v.z, v.w));
            *reinterpret_cast<uint2*>(&xh[br * XSH + col]) = hv;
        }
    } else {
        #pragma unroll
        for (int i = 0; i < 9; i++) {
            int idx = tid + i * THREADS;
            int br  = idx >> 4;
            int col = (idx & 15) << 2;
            int gr  = tile_start + br - 5;
            float4 v = make_float4(0.f, 0.f, 0.f, 0.f);
            if (gr >= 0 && gr < length)
                v = *reinterpret_cast<const float4*>(&X[(size_t)gr * RANK + col]);
            uint2 hv;
            hv.x = h2bits(__floats2half2_rn(v.x, v.y));
            hv.y = h2bits(__floats2half2_rn(v.z, v.w));
            *reinterpret_cast<uint2*>(&xh[br * XSH + col]) = hv;
        }
    }
    // ---- stage W as fp16 ----
    #pragma unroll
    for (int i = 0; i < 4; i++) {
        int idx = tid + i * THREADS;
        int row = idx >> 4;
        int col = (idx & 15) << 2;
        float4 v = *reinterpret_cast<const float4*>(&W[row * RANK + col]);
        uint2 hv;
        hv.x = h2bits(__floats2half2_rn(v.x, v.y));
        hv.y = h2bits(__floats2half2_rn(v.z, v.w));
        *reinterpret_cast<uint2*>(&wh[row * XSH + col]) = hv;
    }
    if (tid < RANK) bsm[tid] = b[tid];
    __syncthreads();   // the ONLY block-wide barrier

    // ldmatrix lane-address bases
    const int nt_row = ((lane >> 4) << 3) + mrow;
    const int nt_kof = ((lane >> 3) & 1) * 8;
    const uint32_t wbase  = sptr(wh) + (uint32_t)((nt_row * XSH + nt_kof) * 2);
    const uint32_t sxbase = sptr(xh) + (uint32_t)(((m0 + nt_row) * XSH + nt_kof) * 2);
    const int tr_row = ((lane >> 3) & 1) * 8 + mrow;
    const int tr_nof = (lane >> 4) * 8;
    const uint32_t obase = sptr(xh) + (uint32_t)(((m0 + tr_row) * XSH + tr_nof) * 2);

    // ---- Phase A: D(16x64/warp) = Xtile * W^T + bias (bias in accumulator) ----
    float acc[8][4];
    {
        const int c = 2 * tg;
        #pragma unroll
        for (int j = 0; j < 8; j++) {
            float2 bb = *reinterpret_cast<const float2*>(&bsm[8 * j + c]);
            acc[j][0] = bb.x; acc[j][1] = bb.y;
            acc[j][2] = bb.x; acc[j][3] = bb.y;
        }
    }
    {
        const uint32_t abase = sptr(xh) +
            (uint32_t)(((m0 + 5 + (mat & 1) * 8 + mrow) * XSH + (mat >> 1) * 8) * 2);
        #pragma unroll
        for (int ks = 0; ks < 4; ks++) {
            uint32_t a0, a1, a2, a3;
            LDSM_X4(a0, a1, a2, a3, abase + ks * 32);
            #pragma unroll
            for (int jj = 0; jj < 4; jj++) {
                uint32_t b0, b1, b2, b3;
                LDSM_X4(b0, b1, b2, b3, wbase + jj * ROW16B + ks * 32);
                HMMA16(acc[2 * jj],     a0, a1, a2, a3, b0, b1);
                HMMA16(acc[2 * jj + 1], a0, a1, a2, a3, b2, b3);
            }
        }
    }

    // ---- v1 = tanh(D) via HW tanh, kept in registers as score A-fragments ----
    uint32_t va[8], vb[8];
    #pragma unroll
    for (int j = 0; j < 8; j++) {
        va[j] = h2bits(__floats2half2_rn(hw_tanh(acc[j][0]), hw_tanh(acc[j][1])));
        vb[j] = h2bits(__floats2half2_rn(hw_tanh(acc[j][2]), hw_tanh(acc[j][3])));
    }

    // ---- Scores: S'(16x32) = V1 * Xnbr^T, A from registers, B via ldmatrix ----
    float sac[4][4];
    #pragma unroll
    for (int j = 0; j < 4; j++)
        #pragma unroll
        for (int q = 0; q < 4; q++) sac[j][q] = 0.f;
    #pragma unroll
    for (int ks = 0; ks < 4; ks++) {
        #pragma unroll
        for (int jj = 0; jj < 2; jj++) {
            uint32_t b0, b1, b2, b3;
            LDSM_X4(b0, b1, b2, b3, sxbase + jj * ROW16B + ks * 32);
            HMMA16(sac[2 * jj],     va[2 * ks], vb[2 * ks], va[2 * ks + 1], vb[2 * ks + 1], b0, b1);
            HMMA16(sac[2 * jj + 1], va[2 * ks], vb[2 * ks], va[2 * ks + 1], vb[2 * ks + 1], b2, b3);
        }
    }

    // ---- softmax in registers (no max shift: scores bounded), probs packed
    //      directly into output-MMA A-fragments ----
    uint32_t pa[2][4];
    {
        float sA = 0.f, sB = 0.f;
        #pragma unroll
        for (int j = 0; j < 4; j++) {
            const int n = 8 * j + 2 * tg;
            sac[j][0] = (n     - gid       >= 0 && n     - gid       < WIN)
                        ? ex2f(sac[j][0] * EXP2_SCALE) : 0.f;
            sac[j][1] = (n + 1 - gid       >= 0 && n + 1 - gid       < WIN)
                        ? ex2f(sac[j][1] * EXP2_SCALE) : 0.f;
            sac[j][2] = (n     - (gid + 8) >= 0 && n     - (gid + 8) < WIN)
                        ? ex2f(sac[j][2] * EXP2_SCALE) : 0.f;
            sac[j][3] = (n + 1 - (gid + 8) >= 0 && n + 1 - (gid + 8) < WIN)
                        ? ex2f(sac[j][3] * EXP2_SCALE) : 0.f;
            sA += sac[j][0] + sac[j][1];
            sB += sac[j][2] + sac[j][3];
        }
        sA += __shfl_xor_sync(0xffffffffu, sA, 1);
        sA += __shfl_xor_sync(0xffffffffu, sA, 2);
        sB += __shfl_xor_sync(0xffffffffu, sB, 1);
        sB += __shfl_xor_sync(0xffffffffu, sB, 2);
        const float invA = __fdividef(1.0f, sA);
        const float invB = __fdividef(1.0f, sB);

        // A-fragment identity: k-chunk ks -> cols 16ks+2tg(+8) = sac[2ks], sac[2ks+1]
        #pragma unroll
        for (int ks = 0; ks < 2; ks++) {
            pa[ks][0] = h2bits(__floats2half2_rn(sac[2 * ks][0] * invA, sac[2 * ks][1] * invA));
            pa[ks][1] = h2bits(__floats2half2_rn(sac[2 * ks][2] * invB, sac[2 * ks][3] * invB));
            pa[ks][2] = h2bits(__floats2half2_rn(sac[2 * ks + 1][0] * invA, sac[2 * ks + 1][1] * invA));
            pa[ks][3] = h2bits(__floats2half2_rn(sac[2 * ks + 1][2] * invB, sac[2 * ks + 1][3] * invB));
        }
    }

    // ---- Output: O(16x64) = S'(16x32) * Xband(32x64); A from registers ----
    {
        float oac[8][4];
        #pragma unroll
        for (int j = 0; j < 8; j++)
            #pragma unroll
            for (int q = 0; q < 4; q++) oac[j][q] = 0.f;

        #pragma unroll
        for (int ks = 0; ks < 2; ks++) {
            #pragma unroll
            for (int jj = 0; jj < 4; jj++) {
                uint32_t b0, b1, b2, b3;
                LDSM_X4T(b0, b1, b2, b3, obase + ks * ROW16B + jj * 32);
                HMMA16(oac[2 * jj],     pa[ks][0], pa[ks][1], pa[ks][2], pa[ks][3], b0, b1);
                HMMA16(oac[2 * jj + 1], pa[ks][0], pa[ks][1], pa[ks][2], pa[ks][3], b2, b3);
            }
        }
        #pragma unroll
        for (int j = 0; j < 8; j++) {
            const int c = 8 * j + 2 * tg;
            const int gr0 = tile_start + m0 + gid;
            const int gr1 = gr0 + 8;
            if (gr0 < length) {
                float2 v = make_float2(oac[j][0], oac[j][1]);
                *reinterpret_cast<float2*>(&out[(size_t)gr0 * RANK + c]) = v;
            }
            if (gr1 < length) {
                float2 v = make_float2(oac[j][2], oac[j][3]);
                *reinterpret_cast<float2*>(&out[(size_t)gr1 * RANK + c]) = v;
            }
        }
    }
}

extern "C" void kernel_launch(void* const* d_in, const int* in_sizes, int n_in,
                              void* d_out, int out_size)
{
    const float* X = (const float*)d_in[0];
    const float* W = (const float*)d_in[1];
    const float* b = (const float*)d_in[2];
    float* out = (float*)d_out;

    const int length = in_sizes[0] / RANK;
    const int grid = (length + TILE - 1) / TILE;
    cudaFuncSetAttribute(attn_window_kernel,
                         cudaFuncAttributeMaxDynamicSharedMemorySize, SMEM_BYTES);
    attn_window_kernel<<<grid, THREADS, SMEM_BYTES>>>(X, W, b, out, length);
}

// round 15
// speedup vs baseline: 1.0106x; 1.0106x over previous
#include <cuda_runtime.h>
#include <cuda_fp16.h>
#include <cstdint>

#define RANK    64
#define WIN     11
#define TILE    128
#define THREADS 256
#define NROWS   144     // staged rows; buffer row br <-> global row tile_start + br - 5
#define XSH     72      // xh row stride in halves (144B, 16B-aligned)
#define ROW16B  (16 * XSH * 2)   // 2304: byte stride of 16 rows

// smem byte offsets
#define XH_OFF   0                    // fp16 X tile: 144*144 = 20736
#define WH_OFF   20736                // fp16 W: 64*144 = 9216
#define BS_OFF   29952                // bias fp32, 256B
#define SMEM_BYTES 30208

// softmax exp base-2 scale: (1/sqrt(64)) * log2(e)
#define EXP2_SCALE 0.18033688011112042f

#define LDSM_X4(r0, r1, r2, r3, a) \
    asm volatile("ldmatrix.sync.aligned.m8n8.x4.shared.b16 {%0,%1,%2,%3}, [%4];" \
        : "=r"(r0), "=r"(r1), "=r"(r2), "=r"(r3) : "r"(a))
#define LDSM_X4T(r0, r1, r2, r3, a) \
    asm volatile("ldmatrix.sync.aligned.m8n8.x4.trans.shared.b16 {%0,%1,%2,%3}, [%4];" \
        : "=r"(r0), "=r"(r1), "=r"(r2), "=r"(r3) : "r"(a))
#define HMMA16(d, a0, a1, a2, a3, b0, b1) \
    asm volatile("mma.sync.aligned.m16n8k16.row.col.f32.f16.f16.f32 " \
        "{%0,%1,%2,%3},{%4,%5,%6,%7},{%8,%9},{%0,%1,%2,%3};" \
        : "+f"((d)[0]), "+f"((d)[1]), "+f"((d)[2]), "+f"((d)[3]) \
        : "r"(a0), "r"(a1), "r"(a2), "r"(a3), "r"(b0), "r"(b1))

__device__ __forceinline__ uint32_t sptr(const void* p) {
    return (uint32_t)__cvta_generic_to_shared(p);
}
__device__ __forceinline__ uint32_t h2bits(__half2 h) {
    return *reinterpret_cast<uint32_t*>(&h);
}
__device__ __forceinline__ float hw_tanh(float x) {
    float r;
    asm("tanh.approx.f32 %0, %1;" : "=f"(r) : "f"(x));
    return r;
}
__device__ __forceinline__ float ex2f(float x) {
    float r;
    asm("ex2.approx.f32 %0, %1;" : "=f"(r) : "f"(x));
    return r;
}

__global__ void __launch_bounds__(THREADS) attn_window_kernel(
    const float* __restrict__ X,   // (L, 64)
    const float* __restrict__ W,   // (64, 64) row-major (out, in)
    const float* __restrict__ b,   // (64,)
    float* __restrict__ out,       // (L, 64)
    int length)
{
    extern __shared__ __align__(16) char sm[];
    __half* xh  = (__half*)(sm + XH_OFF);
    __half* wh  = (__half*)(sm + WH_OFF);
    float*  bsm = (float*)(sm + BS_OFF);

    const int tid  = threadIdx.x;
    const int lane = tid & 31;
    const int wid  = tid >> 5;
    const int gid  = lane >> 2;      // mma group id (0..7)
    const int tg   = lane & 3;       // thread-in-group (0..3)
    const int mat  = lane >> 3;      // ldmatrix matrix id (0..3)
    const int mrow = lane & 7;       // ldmatrix row within matrix
    const int tile_start = blockIdx.x * TILE;
    const int m0 = wid * 16;         // warp's first local row

    // ---- stage X as fp16: interior CTAs skip per-row predication ----
    const bool interior = (tile_start >= 5) && (tile_start + NROWS - 5 <= length);
    if (interior) {
        const float* xb = &X[(size_t)(tile_start - 5) * RANK];
        #pragma unroll
        for (int i = 0; i < 9; i++) {
            int idx = tid + i * THREADS;
            int br  = idx >> 4;
            int col = (idx & 15) << 2;
            float4 v = *reinterpret_cast<const float4*>(&xb[br * RANK + col]);
            uint2 hv;
            hv.x = h2bits(__floats2half2_rn(v.x, v.y));
            hv.y = h2bits(__floats2half2_rn(v.z, v.w));
            *reinterpret_cast<uint2*>(&xh[br * XSH + col]) = hv;
        }
    } else {
        #pragma unroll
        for (int i = 0; i < 9; i++) {
            int idx = tid + i * THREADS;
            int br  = idx >> 4;
            int col = (idx & 15) << 2;
            int gr  = tile_start + br - 5;
            float4 v = make_float4(0.f, 0.f, 0.f, 0.f);
            if (gr >= 0 && gr < length)
                v = *reinterpret_cast<const float4*>(&X[(size_t)gr * RANK + col]);
            uint2 hv;
            hv.x = h2bits(__floats2half2_rn(v.x, v.y));
            hv.y = h2bits(__floats2half2_rn(v.z, v.w));
            *reinterpret_cast<uint2*>(&xh[br * XSH + col]) = hv;
        }
    }
    // ---- stage W as fp16 ----
    #pragma unroll
    for (int i = 0; i < 4; i++) {
        int idx = tid + i * THREADS;
        int row = idx >> 4;
        int col = (idx & 15) << 2;
        float4 v = *reinterpret_cast<const float4*>(&W[row * RANK + col]);
        uint2 hv;
        hv.x = h2bits(__floats2half2_rn(v.x, v.y));
        hv.y = h2bits(__floats2half2_rn(v.z, v.w));
        *reinterpret_cast<uint2*>(&wh[row * XSH + col]) = hv;
    }
    if (tid < RANK) bsm[tid] = b[tid];
    __syncthreads();   // the ONLY block-wide barrier

    // ldmatrix lane-address bases
    const int nt_row = ((lane >> 4) << 3) + mrow;
    const int nt_kof = ((lane >> 3) & 1) * 8;
    const uint32_t wbase  = sptr(wh) + (uint32_t)((nt_row * XSH + nt_kof) * 2);
    const uint32_t sxbase = sptr(xh) + (uint32_t)(((m0 + nt_row) * XSH + nt_kof) * 2);
    const int tr_row = ((lane >> 3) & 1) * 8 + mrow;
    const int tr_nof = (lane >> 4) * 8;
    const uint32_t obase = sptr(xh) + (uint32_t)(((m0 + tr_row) * XSH + tr_nof) * 2);

    // ---- Phase A: D(16x64/warp) = Xtile * W^T + bias (bias in accumulator) ----
    float acc[8][4];
    {
        const int c = 2 * tg;
        #pragma unroll
        for (int j = 0; j < 8; j++) {
            float2 bb = *reinterpret_cast<const float2*>(&bsm[8 * j + c]);
            acc[j][0] = bb.x; acc[j][1] = bb.y;
            acc[j][2] = bb.x; acc[j][3] = bb.y;
        }
    }
    {
        const uint32_t abase = sptr(xh) +
            (uint32_t)(((m0 + 5 + (mat & 1) * 8 + mrow) * XSH + (mat >> 1) * 8) * 2);
        #pragma unroll
        for (int ks = 0; ks < 4; ks++) {
            uint32_t a0, a1, a2, a3;
            LDSM_X4(a0, a1, a2, a3, abase + ks * 32);
            #pragma unroll
            for (int jj = 0; jj < 4; jj++) {
                uint32_t b0, b1, b2, b3;
                LDSM_X4(b0, b1, b2, b3, wbase + jj * ROW16B + ks * 32);
                HMMA16(acc[2 * jj],     a0, a1, a2, a3, b0, b1);
                HMMA16(acc[2 * jj + 1], a0, a1, a2, a3, b2, b3);
            }
        }
    }

    // ---- v1 = tanh(D) via HW tanh, kept in registers as score A-fragments ----
    uint32_t va[8], vb[8];
    #pragma unroll
    for (int j = 0; j < 8; j++) {
        va[j] = h2bits(__floats2half2_rn(hw_tanh(acc[j][0]), hw_tanh(acc[j][1])));
        vb[j] = h2bits(__floats2half2_rn(hw_tanh(acc[j][2]), hw_tanh(acc[j][3])));
    }

    // ---- Scores: S'(16x32) = V1 * Xnbr^T, A from registers, B via ldmatrix ----
    float sac[4][4];
    #pragma unroll
    for (int j = 0; j < 4; j++)
        #pragma unroll
        for (int q = 0; q < 4; q++) sac[j][q] = 0.f;
    #pragma unroll
    for (int ks = 0; ks < 4; ks++) {
        #pragma unroll
        for (int jj = 0; jj < 2; jj++) {
            uint32_t b0, b1, b2, b3;
            LDSM_X4(b0, b1, b2, b3, sxbase + jj * ROW16B + ks * 32);
            HMMA16(sac[2 * jj],     va[2 * ks], vb[2 * ks], va[2 * ks + 1], vb[2 * ks + 1], b0, b1);
            HMMA16(sac[2 * jj + 1], va[2 * ks], vb[2 * ks], va[2 * ks + 1], vb[2 * ks + 1], b2, b3);
        }
    }

    // ---- PREFETCH output-B (ks=0 half): depends only on xh, overlaps the
    //      softmax latency chain below ----
    uint32_t ob[4][4];
    #pragma unroll
    for (int jj = 0; jj < 4; jj++)
        LDSM_X4T(ob[jj][0], ob[jj][1], ob[jj][2], ob[jj][3], obase + jj * 32);

    // ---- softmax in registers (no max shift: scores bounded), probs packed
    //      directly into output-MMA A-fragments ----
    uint32_t pa[2][4];
    {
        float sA0 = 0.f, sA1 = 0.f, sB0 = 0.f, sB1 = 0.f;
        #pragma unroll
        for (int j = 0; j < 4; j++) {
            const int n = 8 * j + 2 * tg;
            sac[j][0] = (n     - gid       >= 0 && n     - gid       < WIN)
                        ? ex2f(sac[j][0] * EXP2_SCALE) : 0.f;
            sac[j][1] = (n + 1 - gid       >= 0 && n + 1 - gid       < WIN)
                        ? ex2f(sac[j][1] * EXP2_SCALE) : 0.f;
            sac[j][2] = (n     - (gid + 8) >= 0 && n     - (gid + 8) < WIN)
                        ? ex2f(sac[j][2] * EXP2_SCALE) : 0.f;
            sac[j][3] = (n + 1 - (gid + 8) >= 0 && n + 1 - (gid + 8) < WIN)
                        ? ex2f(sac[j][3] * EXP2_SCALE) : 0.f;
            sA0 += sac[j][0]; sA1 += sac[j][1];
            sB0 += sac[j][2]; sB1 += sac[j][3];
        }
        float sA = sA0 + sA1;
        float sB = sB0 + sB1;
        sA += __shfl_xor_sync(0xffffffffu, sA, 1);
        sA += __shfl_xor_sync(0xffffffffu, sA, 2);
        sB += __shfl_xor_sync(0xffffffffu, sB, 1);
        sB += __shfl_xor_sync(0xffffffffu, sB, 2);
        const float invA = __fdividef(1.0f, sA);
        const float invB = __fdividef(1.0f, sB);

        // A-fragment identity: k-chunk ks -> cols 16ks+2tg(+8) = sac[2ks], sac[2ks+1]
        #pragma unroll
        for (int ks = 0; ks < 2; ks++) {
            pa[ks][0] = h2bits(__floats2half2_rn(sac[2 * ks][0] * invA, sac[2 * ks][1] * invA));
            pa[ks][1] = h2bits(__floats2half2_rn(sac[2 * ks][2] * invB, sac[2 * ks][3] * invB));
            pa[ks][2] = h2bits(__floats2half2_rn(sac[2 * ks + 1][0] * invA, sac[2 * ks + 1][1] * invA));
            pa[ks][3] = h2bits(__floats2half2_rn(sac[2 * ks + 1][2] * invB, sac[2 * ks + 1][3] * invB));
        }
    }

    // ---- Output: O(16x64) = S'(16x32) * Xband(32x64); A from registers;
    //      ks=0 B from prefetched regs, ks=1 B loaded inline ----
    {
        float oac[8][4];
        #pragma unroll
        for (int j = 0; j < 8; j++)
            #pragma unroll
            for (int q = 0; q < 4; q++) oac[j][q] = 0.f;

        #pragma unroll
        for (int jj = 0; jj < 4; jj++) {
            HMMA16(oac[2 * jj],     pa[0][0], pa[0][1], pa[0][2], pa[0][3], ob[jj][0], ob[jj][1]);
            HMMA16(oac[2 * jj + 1], pa[0][0], pa[0][1], pa[0][2], pa[0][3], ob[jj][2], ob[jj][3]);
        }
        #pragma unroll
        for (int jj = 0; jj < 4; jj++) {
            uint32_t b0, b1, b2, b3;
            LDSM_X4T(b0, b1, b2, b3, obase + ROW16B + jj * 32);
            HMMA16(oac[2 * jj],     pa[1][0], pa[1][1], pa[1][2], pa[1][3], b0, b1);
            HMMA16(oac[2 * jj + 1], pa[1][0], pa[1][1], pa[1][2], pa[1][3], b2, b3);
        }
        #pragma unroll
        for (int j = 0; j < 8; j++) {
            const int c = 8 * j + 2 * tg;
            const int gr0 = tile_start + m0 + gid;
            const int gr1 = gr0 + 8;
            if (gr0 < length) {
                float2 v = make_float2(oac[j][0], oac[j][1]);
                *reinterpret_cast<float2*>(&out[(size_t)gr0 * RANK + c]) = v;
            }
            if (gr1 < length) {
                float2 v = make_float2(oac[j][2], oac[j][3]);
                *reinterpret_cast<float2*>(&out[(size_t)gr1 * RANK + c]) = v;
            }
        }
    }
}

extern "C" void kernel_launch(void* const* d_in, const int* in_sizes, int n_in,
                              void* d_out, int out_size)
{
    const float* X = (const float*)d_in[0];
    const float* W = (const float*)d_in[1];
    const float* b = (const float*)d_in[2];
    float* out = (float*)d_out;

    const int length = in_sizes[0] / RANK;
    const int grid = (length + TILE - 1) / TILE;
    cudaFuncSetAttribute(attn_window_kernel,
                         cudaFuncAttributeMaxDynamicSharedMemorySize, SMEM_BYTES);
    attn_window_kernel<<<grid, THREADS, SMEM_BYTES>>>(X, W, b, out, length);
}